// round 14
// baseline (speedup 1.0000x reference)
#include <cuda_runtime.h>
#include <math.h>
#include <stdint.h>

// ---------------- problem constants ----------------
#define BB 2
#define LL 1024
#define HH 768
#define DI 1536
#define NN 16
#define KC 4          // conv kernel width
#define RR 48
#define TOK (BB*LL)   // 2048 tokens
#define N1 (2*DI*4)   // 12288
#define N2 (2*DI)     // 3072
#define N3 (4*DI)     // 6144

// ---------------- device scratch (no allocs allowed) ----------------
__device__ float g_t1  [(size_t)TOK * N1];   // up-proj act, reused later
__device__ float g_P   [(size_t)TOK * N2];   // proj: cols [0,DI)=hs, [DI,2DI)=gate
__device__ float g_hsc [(size_t)TOK * DI];   // conv+silu output, token-major
__device__ float g_ssmp[(size_t)TOK * 80];   // x_proj output (R + 2N = 80)
__device__ float g_dt  [(size_t)TOK * DI];   // softplus(dt), token-major
__device__ float g_z   [(size_t)TOK * DI];   // scan output * gate, token-major
__device__ float g_dtwT[RR * DI];            // dt_w transposed [R][DI]
__device__ float g_xwT [DI * 80];            // x_proj_w transposed [DI][80]

__device__ __forceinline__ float silu_f(float x) {
    return x / (1.f + __expf(-x));
}

// ===================== mma.sync tf32 helpers =====================
__device__ __forceinline__ uint32_t smem_u32(const void* p) {
    uint32_t a;
    asm("{ .reg .u64 t; cvta.to.shared.u64 t, %1; cvt.u32.u64 %0, t; }"
        : "=r"(a) : "l"(p));
    return a;
}

#define CP_ASYNC16(dst, src) \
    asm volatile("cp.async.cg.shared.global [%0], [%1], 16;" \
                 :: "r"(dst), "l"(src) : "memory")
#define CP_COMMIT() asm volatile("cp.async.commit_group;" ::: "memory")
#define CP_WAIT1()  asm volatile("cp.async.wait_group 1;" ::: "memory")

__device__ __forceinline__ void split_tf32(float x, uint32_t& hi, uint32_t& lo) {
    uint32_t h;
    asm("cvt.rna.tf32.f32 %0, %1;" : "=r"(h) : "f"(x));
    hi = h;
    lo = __float_as_uint(x - __uint_as_float(h));
}

__device__ __forceinline__ void mma_tf32(float* c, const uint32_t* a, const uint32_t* b) {
    asm volatile("mma.sync.aligned.m16n8k8.row.col.f32.tf32.tf32.f32 "
                 "{%0,%1,%2,%3}, {%4,%5,%6,%7}, {%8,%9}, {%0,%1,%2,%3};"
                 : "+f"(c[0]), "+f"(c[1]), "+f"(c[2]), "+f"(c[3])
                 : "r"(a[0]), "r"(a[1]), "r"(a[2]), "r"(a[3]),
                   "r"(b[0]), "r"(b[1]));
}

// =====================================================================
// GEMM NT via mma.sync tf32x3:
//   C[M,N] = A[M,K] (row-major) * B[N,K] (row-major)^T
// 128x64x16 tiles, 128 threads (2x2 warps, 64x32 per warp),
// 2-stage cp.async double-buffer (smem 30KB/CTA so smem no longer
// limits residency), __maxnreg__(112) -> 4 CTAs/SM by regs.
// Requires M%128==0, N%64==0, K%16==0.
// =====================================================================
#define BKT 16
#define STAGES 2
#define AS_STRIDE 20                        // floats per smem row (pad 16 -> 20)
#define A_FLOATS (128 * AS_STRIDE)          // 2560
#define B_FLOATS (64 * AS_STRIDE)           // 1280
#define STAGE_FLOATS (A_FLOATS + B_FLOATS)  // 3840
#define GSMEM_BYTES (STAGES * STAGE_FLOATS * 4)   // 30720

template<bool SILU>
__global__ __maxnreg__(112)
void gemm_tf32_mma(const float* __restrict__ A, const float* __restrict__ B,
                   float* __restrict__ C, int M, int N, int K)
{
    extern __shared__ float S[];
    const int tid  = threadIdx.x;
    const int wid  = tid >> 5;
    const int lane = tid & 31;
    const int gq   = lane >> 2;     // group 0..7
    const int tig  = lane & 3;      // thread-in-group
    const int warp_m = wid & 1;     // 0..1 (64 rows each)
    const int warp_n = wid >> 1;    // 0..1 (32 cols each)
    const int bm = blockIdx.y * 128;
    const int bn = blockIdx.x * 64;
    const uint32_t sb = smem_u32(S);

    float acc[4][4][4];
    #pragma unroll
    for (int i = 0; i < 4; i++)
        #pragma unroll
        for (int j = 0; j < 4; j++)
            #pragma unroll
            for (int r = 0; r < 4; r++) acc[i][j][r] = 0.f;

    const int nk = K / BKT;

    // ---- tile loader ----
    // A: 512 float4 chunks, 4 per thread (rows stride 32 per chunk)
    // B: 256 float4 chunks, 2 per thread
    const int l_row = tid >> 2;           // 0..31
    const int l_c0  = (tid & 3) << 2;     // 0,4,8,12
    const float* Abase = A + (size_t)(bm + l_row) * K + l_c0;
    const float* Bbase = B + (size_t)(bn + l_row) * K + l_c0;
    const uint32_t sA0 = sb + (uint32_t)(l_row * AS_STRIDE + l_c0) * 4;
    const uint32_t sB0 = sb + (uint32_t)(A_FLOATS + l_row * AS_STRIDE + l_c0) * 4;

#define LOAD_TILE(kt, stage) do {                                              \
        const uint32_t so = (uint32_t)(stage) * (STAGE_FLOATS * 4);            \
        const size_t ko = (size_t)(kt) * BKT;                                  \
        CP_ASYNC16(sA0 + so,                        Abase + ko);               \
        CP_ASYNC16(sA0 + so + 32*AS_STRIDE*4,       Abase + ko + (size_t)32*K);\
        CP_ASYNC16(sA0 + so + 64*AS_STRIDE*4,       Abase + ko + (size_t)64*K);\
        CP_ASYNC16(sA0 + so + 96*AS_STRIDE*4,       Abase + ko + (size_t)96*K);\
        CP_ASYNC16(sB0 + so,                        Bbase + ko);               \
        CP_ASYNC16(sB0 + so + 32*AS_STRIDE*4,       Bbase + ko + (size_t)32*K);\
    } while (0)

    // prologue: stages 0,1 in flight
    {
        LOAD_TILE(0, 0); CP_COMMIT();
        LOAD_TILE(1, 1); CP_COMMIT();
    }

    for (int kt = 0; kt < nk; kt++) {
        CP_WAIT1();            // <=1 group pending => stage kt arrived
        __syncthreads();

        const int stage = kt % STAGES;
        const float* sA = S + stage * STAGE_FLOATS + (warp_m * 64) * AS_STRIDE;
        const float* sB = S + stage * STAGE_FLOATS + A_FLOATS + (warp_n * 32) * AS_STRIDE;

        #pragma unroll
        for (int ks = 0; ks < BKT; ks += 8) {
            // B fragments up front: 16 regs, reused across all 4 i
            uint32_t bhi[4][2], blo[4][2];
            #pragma unroll
            for (int j = 0; j < 4; j++) {
                const float* r0 = sB + (j * 8 + gq) * AS_STRIDE + ks + tig;
                split_tf32(r0[0], bhi[j][0], blo[j][0]);
                split_tf32(r0[4], bhi[j][1], blo[j][1]);
            }
            // A fragments on demand per i: 8 regs live
            #pragma unroll
            for (int i = 0; i < 4; i++) {
                const float* r0 = sA + (i * 16 + gq) * AS_STRIDE + ks + tig;
                const float* r1 = r0 + 8 * AS_STRIDE;
                uint32_t ahi[4], alo[4];
                split_tf32(r0[0], ahi[0], alo[0]);
                split_tf32(r1[0], ahi[1], alo[1]);
                split_tf32(r0[4], ahi[2], alo[2]);
                split_tf32(r1[4], ahi[3], alo[3]);
                #pragma unroll
                for (int j = 0; j < 4; j++) {
                    mma_tf32(acc[i][j], ahi, bhi[j]);
                    mma_tf32(acc[i][j], ahi, blo[j]);
                    mma_tf32(acc[i][j], alo, bhi[j]);
                }
            }
        }
        __syncthreads();       // all warps done with stage kt before overwrite

        const int nt = kt + 2;
        if (nt < nk) LOAD_TILE(nt, nt % STAGES);  // into buffer kt%2
        CP_COMMIT();
    }
#undef LOAD_TILE

    // epilogue
    #pragma unroll
    for (int i = 0; i < 4; i++) {
        const int row0 = bm + warp_m * 64 + i * 16 + gq;
        #pragma unroll
        for (int j = 0; j < 4; j++) {
            const int col = bn + warp_n * 32 + j * 8 + tig * 2;
            float2 v0 = make_float2(acc[i][j][0], acc[i][j][1]);
            float2 v1 = make_float2(acc[i][j][2], acc[i][j][3]);
            if (SILU) {
                v0.x = silu_f(v0.x); v0.y = silu_f(v0.y);
                v1.x = silu_f(v1.x); v1.y = silu_f(v1.y);
            }
            *(float2*)&C[(size_t)row0 * N + col]       = v0;
            *(float2*)&C[(size_t)(row0 + 8) * N + col] = v1;
        }
    }
}

// ---------------------------------------------------------------
// small-weight transpose: dst[c*rows + r] = src[r*cols + c]
// ---------------------------------------------------------------
__global__ void transpose_small(const float* __restrict__ src, float* __restrict__ dst,
                                int rows, int cols)
{
    int i = blockIdx.x * blockDim.x + threadIdx.x;
    if (i < rows * cols) {
        int r = i / cols, c = i % cols;
        dst[(size_t)c * rows + r] = src[i];
    }
}

// ---------------------------------------------------------------
// depthwise causal conv (K=4) + bias + SiLU.
// ---------------------------------------------------------------
__global__ void conv_silu_kernel(const float* __restrict__ conv_w,
                                 const float* __restrict__ conv_b)
{
    int idx = blockIdx.x * blockDim.x + threadIdx.x;  // over TOK*DI
    if (idx >= TOK * DI) return;
    int d = idx % DI;
    int t = idx / DI;
    int l = t % LL;
    int b = t / LL;

    float4 w = *(const float4*)&conv_w[d * KC];
    float acc = conv_b[d];
    const float* Pb = g_P + (size_t)b * LL * N2 + d;
    float wj[4] = {w.x, w.y, w.z, w.w};
    #pragma unroll
    for (int j = 0; j < KC; j++) {
        int ls = l - (KC - 1) + j;
        if (ls >= 0) acc = fmaf(wj[j], Pb[(size_t)ls * N2], acc);
    }
    g_hsc[idx] = silu_f(acc);
}

// ---------------------------------------------------------------
// x_proj: ssmp[t,k] = sum_d hsc[t,d] * xwT[d,k],  k in [0,80)
// ---------------------------------------------------------------
__global__ void xproj_kernel()
{
    __shared__ float sh[DI];
    const int t = blockIdx.x;
    for (int i = threadIdx.x; i < DI; i += blockDim.x)
        sh[i] = g_hsc[(size_t)t * DI + i];
    __syncthreads();
    const int k = threadIdx.x;
    if (k < 80) {
        float acc = 0.f;
        #pragma unroll 8
        for (int d = 0; d < DI; d++)
            acc = fmaf(sh[d], g_xwT[d * 80 + k], acc);
        g_ssmp[(size_t)t * 80 + k] = acc;
    }
}

// ---------------------------------------------------------------
// dt: dt[t,d] = softplus( ts[t,:] @ dt_w[d,:] + dt_b[d] )
// ---------------------------------------------------------------
__global__ void dt_kernel(const float* __restrict__ dt_b)
{
    __shared__ float ts[RR];
    const int t = blockIdx.x;
    if (threadIdx.x < RR) ts[threadIdx.x] = g_ssmp[(size_t)t * 80 + threadIdx.x];
    __syncthreads();
    for (int d = threadIdx.x; d < DI; d += blockDim.x) {
        float acc = dt_b[d];
        #pragma unroll
        for (int r = 0; r < RR; r++)
            acc = fmaf(ts[r], g_dtwT[r * DI + d], acc);
        float sp = (acc > 20.f) ? acc : log1pf(expf(acc));
        g_dt[(size_t)t * DI + d] = sp;
    }
}

// ---------------------------------------------------------------
// selective scan. thread per (b,d), 16-state in registers.
// ---------------------------------------------------------------
__global__ void scan_kernel(const float* __restrict__ A_log,
                            const float* __restrict__ Dp)
{
    const int d = blockIdx.x * blockDim.x + threadIdx.x;
    const int b = blockIdx.y;
    if (d >= DI) return;

    float Arow[NN];
    #pragma unroll
    for (int n = 0; n < NN; n++) Arow[n] = -expf(A_log[d * NN + n]);
    const float Dd = Dp[d];

    float s[NN];
    #pragma unroll
    for (int n = 0; n < NN; n++) s[n] = 0.f;

    for (int l = 0; l < LL; l++) {
        const size_t t = (size_t)b * LL + l;
        const float dtv = g_dt[t * DI + d];
        const float u   = g_hsc[t * DI + d];
        const float gte = g_P[t * N2 + DI + d];
        const float* bc = g_ssmp + t * 80 + RR;
        const float dtu = dtv * u;
        float y = 0.f;
        #pragma unroll
        for (int n = 0; n < NN; n++) {
            const float Bn = __ldg(bc + n);
            const float Cn = __ldg(bc + NN + n);
            const float dA = __expf(dtv * Arow[n]);
            s[n] = fmaf(dA, s[n], dtu * Bn);
            y = fmaf(s[n], Cn, y);
        }
        float zz = fmaf(u, Dd, y);
        zz *= silu_f(gte);
        g_z[t * DI + d] = zz;
    }
}

// ---------------------------------------------------------------
extern "C" void kernel_launch(void* const* d_in, const int* in_sizes, int n_in,
                              void* d_out, int out_size)
{
    const float* x          = (const float*)d_in[0];
    const float* in_up_w    = (const float*)d_in[1];
    const float* in_down_w  = (const float*)d_in[2];
    const float* conv_w     = (const float*)d_in[3];
    const float* conv_b     = (const float*)d_in[4];
    const float* x_proj_w   = (const float*)d_in[5];
    const float* dt_w       = (const float*)d_in[6];
    const float* dt_b       = (const float*)d_in[7];
    const float* A_log      = (const float*)d_in[8];
    const float* Dp         = (const float*)d_in[9];
    const float* out_up_w   = (const float*)d_in[10];
    const float* out_down_w = (const float*)d_in[11];
    float* out = (float*)d_out;

    float *t1, *P, *z, *xwT, *dtwT;
    cudaGetSymbolAddress((void**)&t1, g_t1);
    cudaGetSymbolAddress((void**)&P,  g_P);
    cudaGetSymbolAddress((void**)&z,  g_z);
    cudaGetSymbolAddress((void**)&xwT,  g_xwT);
    cudaGetSymbolAddress((void**)&dtwT, g_dtwT);

    static int attr_done = 0;
    if (!attr_done) {
        cudaFuncSetAttribute(gemm_tf32_mma<true >,
                             cudaFuncAttributeMaxDynamicSharedMemorySize, GSMEM_BYTES);
        cudaFuncSetAttribute(gemm_tf32_mma<false>,
                             cudaFuncAttributeMaxDynamicSharedMemorySize, GSMEM_BYTES);
        attr_done = 1;
    }

    // independent small transposes first
    transpose_small<<<(80*DI + 255)/256, 256>>>(x_proj_w, xwT, 80, DI);
    transpose_small<<<(DI*RR + 255)/256, 256>>>(dt_w, dtwT, DI, RR);

    // 1) up-proj + SiLU : [TOK,HH] x [N1,HH]^T -> [TOK,N1]
    gemm_tf32_mma<true ><<<dim3(N1/64, TOK/128), 128, GSMEM_BYTES>>>(x, in_up_w, t1, TOK, N1, HH);
    // 2) down-proj : [TOK,N1] x [N2,N1]^T -> [TOK,N2]  (hs | gate)
    gemm_tf32_mma<false><<<dim3(N2/64, TOK/128), 128, GSMEM_BYTES>>>(t1, in_down_w, P, TOK, N2, N1);
    // 3) depthwise causal conv + SiLU -> hsc (token-major)
    conv_silu_kernel<<<(TOK*DI + 255)/256, 256>>>(conv_w, conv_b);
    // 4) x_proj -> [TOK,80]
    xproj_kernel<<<TOK, 96>>>();
    // 5) dt = softplus(ts @ dt_w^T + dt_b)
    dt_kernel<<<TOK, 256>>>(dt_b);
    // 6) selective scan + D skip + gate -> z
    scan_kernel<<<dim3(DI/128, BB), 128>>>(A_log, Dp);
    // 7) out up-proj + SiLU : [TOK,DI] x [N3,DI]^T -> [TOK,N3]
    gemm_tf32_mma<true ><<<dim3(N3/64, TOK/128), 128, GSMEM_BYTES>>>(z, out_up_w, t1, TOK, N3, DI);
    // 8) out down-proj : [TOK,N3] x [HH,N3]^T -> [TOK,HH]
    gemm_tf32_mma<false><<<dim3(HH/64, TOK/128), 128, GSMEM_BYTES>>>(t1, out_down_w, out, TOK, HH, N3);
}

// round 15
// speedup vs baseline: 1.0327x; 1.0327x over previous
#include <cuda_runtime.h>
#include <math.h>
#include <stdint.h>

// ---------------- problem constants ----------------
#define BB 2
#define LL 1024
#define HH 768
#define DI 1536
#define NN 16
#define KC 4          // conv kernel width
#define RR 48
#define TOK (BB*LL)   // 2048 tokens
#define N1 (2*DI*4)   // 12288
#define N2 (2*DI)     // 3072
#define N3 (4*DI)     // 6144

// ---------------- device scratch (no allocs allowed) ----------------
__device__ float g_t1  [(size_t)TOK * N1];   // up-proj act, reused later
__device__ float g_P   [(size_t)TOK * N2];   // proj: cols [0,DI)=hs, [DI,2DI)=gate
__device__ float g_hsc [(size_t)TOK * DI];   // conv+silu output, token-major
__device__ float g_ssmp[(size_t)TOK * 80];   // x_proj output (R + 2N = 80)
__device__ float g_dt  [(size_t)TOK * DI];   // softplus(dt), token-major
__device__ float g_z   [(size_t)TOK * DI];   // scan output * gate, token-major
__device__ float g_dtwT[RR * DI];            // dt_w transposed [R][DI]
__device__ float g_xwT [DI * 80];            // x_proj_w transposed [DI][80]

__device__ __forceinline__ float silu_f(float x) {
    return x / (1.f + __expf(-x));
}

// ===================== mma.sync tf32 helpers =====================
__device__ __forceinline__ uint32_t smem_u32(const void* p) {
    uint32_t a;
    asm("{ .reg .u64 t; cvta.to.shared.u64 t, %1; cvt.u32.u64 %0, t; }"
        : "=r"(a) : "l"(p));
    return a;
}

#define CP_ASYNC16(dst, src) \
    asm volatile("cp.async.cg.shared.global [%0], [%1], 16;" \
                 :: "r"(dst), "l"(src) : "memory")
#define CP_COMMIT() asm volatile("cp.async.commit_group;" ::: "memory")
#define CP_WAIT1()  asm volatile("cp.async.wait_group 1;" ::: "memory")

__device__ __forceinline__ void split_tf32(float x, uint32_t& hi, uint32_t& lo) {
    uint32_t h;
    asm("cvt.rna.tf32.f32 %0, %1;" : "=r"(h) : "f"(x));
    hi = h;
    lo = __float_as_uint(x - __uint_as_float(h));
}

// NOTE: non-volatile. Register constraints carry all true dependencies;
// ptxas is free to schedule/interleave MMAs to hide HMMA latency.
__device__ __forceinline__ void mma_tf32(float* c, const uint32_t* a, const uint32_t* b) {
    asm("mma.sync.aligned.m16n8k8.row.col.f32.tf32.tf32.f32 "
        "{%0,%1,%2,%3}, {%4,%5,%6,%7}, {%8,%9}, {%0,%1,%2,%3};"
        : "+f"(c[0]), "+f"(c[1]), "+f"(c[2]), "+f"(c[3])
        : "r"(a[0]), "r"(a[1]), "r"(a[2]), "r"(a[3]),
          "r"(b[0]), "r"(b[1]));
}

// =====================================================================
// GEMM NT via mma.sync tf32x3:
//   C[M,N] = A[M,K] (row-major) * B[N,K] (row-major)^T
// 128x64x16 tiles, 128 threads (2x2 warps, 64x32 per warp),
// 3-stage cp.async pipeline. MMAs issued in variant sweeps so
// same-accumulator reuse distance is 4 (breaks RAW chains).
// Requires M%128==0, N%64==0, K%16==0.
// =====================================================================
#define BKT 16
#define STAGES 3
#define AS_STRIDE 20                        // floats per smem row (pad 16 -> 20)
#define A_FLOATS (128 * AS_STRIDE)          // 2560
#define B_FLOATS (64 * AS_STRIDE)           // 1280
#define STAGE_FLOATS (A_FLOATS + B_FLOATS)  // 3840
#define GSMEM_BYTES (STAGES * STAGE_FLOATS * 4)   // 46080

template<bool SILU>
__global__ __maxnreg__(112)
void gemm_tf32_mma(const float* __restrict__ A, const float* __restrict__ B,
                   float* __restrict__ C, int M, int N, int K)
{
    extern __shared__ float S[];
    const int tid  = threadIdx.x;
    const int wid  = tid >> 5;
    const int lane = tid & 31;
    const int gq   = lane >> 2;     // group 0..7
    const int tig  = lane & 3;      // thread-in-group
    const int warp_m = wid & 1;     // 0..1 (64 rows each)
    const int warp_n = wid >> 1;    // 0..1 (32 cols each)
    const int bm = blockIdx.y * 128;
    const int bn = blockIdx.x * 64;
    const uint32_t sb = smem_u32(S);

    float acc[4][4][4];
    #pragma unroll
    for (int i = 0; i < 4; i++)
        #pragma unroll
        for (int j = 0; j < 4; j++)
            #pragma unroll
            for (int r = 0; r < 4; r++) acc[i][j][r] = 0.f;

    const int nk = K / BKT;

    // ---- tile loader ----
    // A: 512 float4 chunks, 4 per thread (rows stride 32 per chunk)
    // B: 256 float4 chunks, 2 per thread
    const int l_row = tid >> 2;           // 0..31
    const int l_c0  = (tid & 3) << 2;     // 0,4,8,12
    const float* Abase = A + (size_t)(bm + l_row) * K + l_c0;
    const float* Bbase = B + (size_t)(bn + l_row) * K + l_c0;
    const uint32_t sA0 = sb + (uint32_t)(l_row * AS_STRIDE + l_c0) * 4;
    const uint32_t sB0 = sb + (uint32_t)(A_FLOATS + l_row * AS_STRIDE + l_c0) * 4;

#define LOAD_TILE(kt, stage) do {                                              \
        const uint32_t so = (uint32_t)(stage) * (STAGE_FLOATS * 4);            \
        const size_t ko = (size_t)(kt) * BKT;                                  \
        CP_ASYNC16(sA0 + so,                        Abase + ko);               \
        CP_ASYNC16(sA0 + so + 32*AS_STRIDE*4,       Abase + ko + (size_t)32*K);\
        CP_ASYNC16(sA0 + so + 64*AS_STRIDE*4,       Abase + ko + (size_t)64*K);\
        CP_ASYNC16(sA0 + so + 96*AS_STRIDE*4,       Abase + ko + (size_t)96*K);\
        CP_ASYNC16(sB0 + so,                        Bbase + ko);               \
        CP_ASYNC16(sB0 + so + 32*AS_STRIDE*4,       Bbase + ko + (size_t)32*K);\
    } while (0)

    // prologue: stages 0,1 in flight
    {
        LOAD_TILE(0, 0); CP_COMMIT();
        LOAD_TILE(1, 1); CP_COMMIT();
    }

    for (int kt = 0; kt < nk; kt++) {
        CP_WAIT1();
        __syncthreads();

        const int stage = kt % STAGES;
        const float* sA = S + stage * STAGE_FLOATS + (warp_m * 64) * AS_STRIDE;
        const float* sB = S + stage * STAGE_FLOATS + A_FLOATS + (warp_n * 32) * AS_STRIDE;

        #pragma unroll
        for (int ks = 0; ks < BKT; ks += 8) {
            // B fragments up front: 16 regs, reused across all 4 i
            uint32_t bhi[4][2], blo[4][2];
            #pragma unroll
            for (int j = 0; j < 4; j++) {
                const float* r0 = sB + (j * 8 + gq) * AS_STRIDE + ks + tig;
                split_tf32(r0[0], bhi[j][0], blo[j][0]);
                split_tf32(r0[4], bhi[j][1], blo[j][1]);
            }
            // A fragments on demand per i; MMAs in variant sweeps:
            // same accumulator touched every 4th MMA, not back-to-back.
            #pragma unroll
            for (int i = 0; i < 4; i++) {
                const float* r0 = sA + (i * 16 + gq) * AS_STRIDE + ks + tig;
                const float* r1 = r0 + 8 * AS_STRIDE;
                uint32_t ahi[4], alo[4];
                split_tf32(r0[0], ahi[0], alo[0]);
                split_tf32(r1[0], ahi[1], alo[1]);
                split_tf32(r0[4], ahi[2], alo[2]);
                split_tf32(r1[4], ahi[3], alo[3]);
                #pragma unroll
                for (int j = 0; j < 4; j++) mma_tf32(acc[i][j], ahi, bhi[j]);
                #pragma unroll
                for (int j = 0; j < 4; j++) mma_tf32(acc[i][j], ahi, blo[j]);
                #pragma unroll
                for (int j = 0; j < 4; j++) mma_tf32(acc[i][j], alo, bhi[j]);
            }
        }
        __syncthreads();

        const int nt = kt + 2;
        if (nt < nk) LOAD_TILE(nt, nt % STAGES);
        CP_COMMIT();
    }
#undef LOAD_TILE

    // epilogue
    #pragma unroll
    for (int i = 0; i < 4; i++) {
        const int row0 = bm + warp_m * 64 + i * 16 + gq;
        #pragma unroll
        for (int j = 0; j < 4; j++) {
            const int col = bn + warp_n * 32 + j * 8 + tig * 2;
            float2 v0 = make_float2(acc[i][j][0], acc[i][j][1]);
            float2 v1 = make_float2(acc[i][j][2], acc[i][j][3]);
            if (SILU) {
                v0.x = silu_f(v0.x); v0.y = silu_f(v0.y);
                v1.x = silu_f(v1.x); v1.y = silu_f(v1.y);
            }
            *(float2*)&C[(size_t)row0 * N + col]       = v0;
            *(float2*)&C[(size_t)(row0 + 8) * N + col] = v1;
        }
    }
}

// ---------------------------------------------------------------
// small-weight transpose: dst[c*rows + r] = src[r*cols + c]
// ---------------------------------------------------------------
__global__ void transpose_small(const float* __restrict__ src, float* __restrict__ dst,
                                int rows, int cols)
{
    int i = blockIdx.x * blockDim.x + threadIdx.x;
    if (i < rows * cols) {
        int r = i / cols, c = i % cols;
        dst[(size_t)c * rows + r] = src[i];
    }
}

// ---------------------------------------------------------------
// depthwise causal conv (K=4) + bias + SiLU.
// ---------------------------------------------------------------
__global__ void conv_silu_kernel(const float* __restrict__ conv_w,
                                 const float* __restrict__ conv_b)
{
    int idx = blockIdx.x * blockDim.x + threadIdx.x;  // over TOK*DI
    if (idx >= TOK * DI) return;
    int d = idx % DI;
    int t = idx / DI;
    int l = t % LL;
    int b = t / LL;

    float4 w = *(const float4*)&conv_w[d * KC];
    float acc = conv_b[d];
    const float* Pb = g_P + (size_t)b * LL * N2 + d;
    float wj[4] = {w.x, w.y, w.z, w.w};
    #pragma unroll
    for (int j = 0; j < KC; j++) {
        int ls = l - (KC - 1) + j;
        if (ls >= 0) acc = fmaf(wj[j], Pb[(size_t)ls * N2], acc);
    }
    g_hsc[idx] = silu_f(acc);
}

// ---------------------------------------------------------------
// x_proj: ssmp[t,k] = sum_d hsc[t,d] * xwT[d,k],  k in [0,80)
// ---------------------------------------------------------------
__global__ void xproj_kernel()
{
    __shared__ float sh[DI];
    const int t = blockIdx.x;
    for (int i = threadIdx.x; i < DI; i += blockDim.x)
        sh[i] = g_hsc[(size_t)t * DI + i];
    __syncthreads();
    const int k = threadIdx.x;
    if (k < 80) {
        float acc = 0.f;
        #pragma unroll 8
        for (int d = 0; d < DI; d++)
            acc = fmaf(sh[d], g_xwT[d * 80 + k], acc);
        g_ssmp[(size_t)t * 80 + k] = acc;
    }
}

// ---------------------------------------------------------------
// dt: dt[t,d] = softplus( ts[t,:] @ dt_w[d,:] + dt_b[d] )
// ---------------------------------------------------------------
__global__ void dt_kernel(const float* __restrict__ dt_b)
{
    __shared__ float ts[RR];
    const int t = blockIdx.x;
    if (threadIdx.x < RR) ts[threadIdx.x] = g_ssmp[(size_t)t * 80 + threadIdx.x];
    __syncthreads();
    for (int d = threadIdx.x; d < DI; d += blockDim.x) {
        float acc = dt_b[d];
        #pragma unroll
        for (int r = 0; r < RR; r++)
            acc = fmaf(ts[r], g_dtwT[r * DI + d], acc);
        float sp = (acc > 20.f) ? acc : log1pf(expf(acc));
        g_dt[(size_t)t * DI + d] = sp;
    }
}

// ---------------------------------------------------------------
// selective scan. thread per (b,d), 16-state in registers.
// ---------------------------------------------------------------
__global__ void scan_kernel(const float* __restrict__ A_log,
                            const float* __restrict__ Dp)
{
    const int d = blockIdx.x * blockDim.x + threadIdx.x;
    const int b = blockIdx.y;
    if (d >= DI) return;

    float Arow[NN];
    #pragma unroll
    for (int n = 0; n < NN; n++) Arow[n] = -expf(A_log[d * NN + n]);
    const float Dd = Dp[d];

    float s[NN];
    #pragma unroll
    for (int n = 0; n < NN; n++) s[n] = 0.f;

    for (int l = 0; l < LL; l++) {
        const size_t t = (size_t)b * LL + l;
        const float dtv = g_dt[t * DI + d];
        const float u   = g_hsc[t * DI + d];
        const float gte = g_P[t * N2 + DI + d];
        const float* bc = g_ssmp + t * 80 + RR;
        const float dtu = dtv * u;
        float y = 0.f;
        #pragma unroll
        for (int n = 0; n < NN; n++) {
            const float Bn = __ldg(bc + n);
            const float Cn = __ldg(bc + NN + n);
            const float dA = __expf(dtv * Arow[n]);
            s[n] = fmaf(dA, s[n], dtu * Bn);
            y = fmaf(s[n], Cn, y);
        }
        float zz = fmaf(u, Dd, y);
        zz *= silu_f(gte);
        g_z[t * DI + d] = zz;
    }
}

// ---------------------------------------------------------------
extern "C" void kernel_launch(void* const* d_in, const int* in_sizes, int n_in,
                              void* d_out, int out_size)
{
    const float* x          = (const float*)d_in[0];
    const float* in_up_w    = (const float*)d_in[1];
    const float* in_down_w  = (const float*)d_in[2];
    const float* conv_w     = (const float*)d_in[3];
    const float* conv_b     = (const float*)d_in[4];
    const float* x_proj_w   = (const float*)d_in[5];
    const float* dt_w       = (const float*)d_in[6];
    const float* dt_b       = (const float*)d_in[7];
    const float* A_log      = (const float*)d_in[8];
    const float* Dp         = (const float*)d_in[9];
    const float* out_up_w   = (const float*)d_in[10];
    const float* out_down_w = (const float*)d_in[11];
    float* out = (float*)d_out;

    float *t1, *P, *z, *xwT, *dtwT;
    cudaGetSymbolAddress((void**)&t1, g_t1);
    cudaGetSymbolAddress((void**)&P,  g_P);
    cudaGetSymbolAddress((void**)&z,  g_z);
    cudaGetSymbolAddress((void**)&xwT,  g_xwT);
    cudaGetSymbolAddress((void**)&dtwT, g_dtwT);

    static int attr_done = 0;
    if (!attr_done) {
        cudaFuncSetAttribute(gemm_tf32_mma<true >,
                             cudaFuncAttributeMaxDynamicSharedMemorySize, GSMEM_BYTES);
        cudaFuncSetAttribute(gemm_tf32_mma<false>,
                             cudaFuncAttributeMaxDynamicSharedMemorySize, GSMEM_BYTES);
        attr_done = 1;
    }

    // independent small transposes first
    transpose_small<<<(80*DI + 255)/256, 256>>>(x_proj_w, xwT, 80, DI);
    transpose_small<<<(DI*RR + 255)/256, 256>>>(dt_w, dtwT, DI, RR);

    // 1) up-proj + SiLU : [TOK,HH] x [N1,HH]^T -> [TOK,N1]
    gemm_tf32_mma<true ><<<dim3(N1/64, TOK/128), 128, GSMEM_BYTES>>>(x, in_up_w, t1, TOK, N1, HH);
    // 2) down-proj : [TOK,N1] x [N2,N1]^T -> [TOK,N2]  (hs | gate)
    gemm_tf32_mma<false><<<dim3(N2/64, TOK/128), 128, GSMEM_BYTES>>>(t1, in_down_w, P, TOK, N2, N1);
    // 3) depthwise causal conv + SiLU -> hsc (token-major)
    conv_silu_kernel<<<(TOK*DI + 255)/256, 256>>>(conv_w, conv_b);
    // 4) x_proj -> [TOK,80]
    xproj_kernel<<<TOK, 96>>>();
    // 5) dt = softplus(ts @ dt_w^T + dt_b)
    dt_kernel<<<TOK, 256>>>(dt_b);
    // 6) selective scan + D skip + gate -> z
    scan_kernel<<<dim3(DI/128, BB), 128>>>(A_log, Dp);
    // 7) out up-proj + SiLU : [TOK,DI] x [N3,DI]^T -> [TOK,N3]
    gemm_tf32_mma<true ><<<dim3(N3/64, TOK/128), 128, GSMEM_BYTES>>>(z, out_up_w, t1, TOK, N3, DI);
    // 8) out down-proj : [TOK,N3] x [HH,N3]^T -> [TOK,HH]
    gemm_tf32_mma<false><<<dim3(HH/64, TOK/128), 128, GSMEM_BYTES>>>(t1, out_down_w, out, TOK, HH, N3);
}

// round 16
// speedup vs baseline: 1.1095x; 1.0744x over previous
#include <cuda_runtime.h>
#include <math.h>
#include <stdint.h>

// ---------------- problem constants ----------------
#define BB 2
#define LL 1024
#define HH 768
#define DI 1536
#define NN 16
#define KC 4          // conv kernel width
#define RR 48
#define TOK (BB*LL)   // 2048 tokens
#define N1 (2*DI*4)   // 12288
#define N2 (2*DI)     // 3072
#define N3 (4*DI)     // 6144

// ---------------- device scratch (no allocs allowed) ----------------
// fragment-major hi/lo planes for every GEMM operand
__device__ float g_xh [(size_t)TOK*HH], g_xl [(size_t)TOK*HH];
__device__ float g_w1h[(size_t)N1*HH],  g_w1l[(size_t)N1*HH];
__device__ float g_t1h[(size_t)TOK*N1], g_t1l[(size_t)TOK*N1];
__device__ float g_w2h[(size_t)N2*N1],  g_w2l[(size_t)N2*N1];
__device__ float g_zh [(size_t)TOK*DI], g_zl [(size_t)TOK*DI];
__device__ float g_w3h[(size_t)N3*DI],  g_w3l[(size_t)N3*DI];
__device__ float g_t2h[(size_t)TOK*N3], g_t2l[(size_t)TOK*N3];
__device__ float g_w4h[(size_t)HH*N3],  g_w4l[(size_t)HH*N3];

__device__ float g_P   [(size_t)TOK * N2];   // proj: cols [0,DI)=hs, [DI,2DI)=gate
__device__ float g_hsc [(size_t)TOK * DI];   // conv+silu output, token-major
__device__ float g_ssmp[(size_t)TOK * 80];   // x_proj output (R + 2N = 80)
__device__ float g_dt  [(size_t)TOK * DI];   // softplus(dt), token-major
__device__ float g_dtwT[RR * DI];            // dt_w transposed [R][DI]
__device__ float g_xwT [DI * 80];            // x_proj_w transposed [DI][80]

__device__ __forceinline__ float silu_f(float x) {
    return x / (1.f + __expf(-x));
}

// ===================== helpers =====================
__device__ __forceinline__ uint32_t smem_u32(const void* p) {
    uint32_t a;
    asm("{ .reg .u64 t; cvta.to.shared.u64 t, %1; cvt.u32.u64 %0, t; }"
        : "=r"(a) : "l"(p));
    return a;
}

#define CP_ASYNC16(dst, src) \
    asm volatile("cp.async.cg.shared.global [%0], [%1], 16;" \
                 :: "r"(dst), "l"(src) : "memory")
#define CP_COMMIT() asm volatile("cp.async.commit_group;" ::: "memory")
#define CP_WAIT1()  asm volatile("cp.async.wait_group 1;" ::: "memory")

__device__ __forceinline__ float tf32_rna(float x) {
    uint32_t u;
    asm("cvt.rna.tf32.f32 %0, %1;" : "=r"(u) : "f"(x));
    return __uint_as_float(u);
}

// non-volatile: ptxas may schedule freely; reg constraints carry deps
__device__ __forceinline__ void mma_tf32(float* c, const uint32_t* a, const uint32_t* b) {
    asm("mma.sync.aligned.m16n8k8.row.col.f32.tf32.tf32.f32 "
        "{%0,%1,%2,%3}, {%4,%5,%6,%7}, {%8,%9}, {%0,%1,%2,%3};"
        : "+f"(c[0]), "+f"(c[1]), "+f"(c[2]), "+f"(c[3])
        : "r"(a[0]), "r"(a[1]), "r"(a[2]), "r"(a[3]),
          "r"(b[0]), "r"(b[1]));
}

// frag-major index for an A-operand element (m,n) of a matrix with row-len N
__device__ __forceinline__ size_t afrag_idx(int m, int n, int N) {
    return ((size_t)((m >> 4) * (N >> 3) + (n >> 3)) * 32
            + ((m & 7) * 4 + (n & 3))) * 4
           + ((m >> 3) & 1) + 2 * ((n >> 2) & 1);
}

// split+store one epilogue element into next-GEMM A-frag hi/lo planes
__device__ __forceinline__ void store_afrag(float* Ch, float* Cl,
                                            int m, int n, int N, float v) {
    float h = tf32_rna(v);
    size_t f = afrag_idx(m, n, N);
    Ch[f] = h;
    Cl[f] = v - h;
}

// =====================================================================
// split kernels: row-major fp32 -> frag-major hi/lo planes
// A-operand: 16-row tiles, 4 words/lane.  B-operand: 8-row tiles, 2 words/lane.
// =====================================================================
__global__ void splitA_frag(const float* __restrict__ src,
                            float* __restrict__ hi, float* __restrict__ lo,
                            int R, int K)
{
    int idx = blockIdx.x * blockDim.x + threadIdx.x;
    if (idx >= R * K) return;
    int r = idx / K, c = idx % K;
    float x = src[idx];
    float h = tf32_rna(x);
    size_t f = afrag_idx(r, c, K);
    hi[f] = h;
    lo[f] = x - h;
}

__global__ void splitB_frag(const float* __restrict__ src,
                            float* __restrict__ hi, float* __restrict__ lo,
                            int R, int K)
{
    int idx = blockIdx.x * blockDim.x + threadIdx.x;
    if (idx >= R * K) return;
    int r = idx / K, c = idx % K;
    float x = src[idx];
    float h = tf32_rna(x);
    size_t f = ((size_t)((r >> 3) * (K >> 3) + (c >> 3)) * 32
                + ((r & 7) * 4 + (c & 3))) * 2
               + ((c >> 2) & 1);
    hi[f] = h;
    lo[f] = x - h;
}

// =====================================================================
// GEMM NT tf32x3 on pre-split frag-major operands.
//   C[M,N] = (Ah+Al)[M,K] * (Bh+Bl)[N,K]^T  (hi*hi + hi*lo + lo*hi)
// 128x64x16 tiles, 128 threads (2x2 warps, 64x32 per warp),
// 3-stage cp.async pipeline. Inner loop = LDS.128/LDS.64 + MMA only.
// smem stage (words): Ahi[2048] Alo[2048] Bhi[1024] Blo[1024] = 6144.
// =====================================================================
#define STAGES 3
#define STAGE_WORDS 6144
#define GSMEM_BYTES (STAGES * STAGE_WORDS * 4)   // 73728

template<bool SILU, bool SPLIT_OUT>
__global__ __maxnreg__(112)
void gemm_frag(const float* __restrict__ Ah, const float* __restrict__ Al,
               const float* __restrict__ Bh, const float* __restrict__ Bl,
               float* __restrict__ C, float* __restrict__ Ch, float* __restrict__ Cl,
               int M, int N, int K)
{
    extern __shared__ float S[];
    const int tid  = threadIdx.x;
    const int wid  = tid >> 5;
    const int lane = tid & 31;
    const int gq   = lane >> 2;
    const int tig  = lane & 3;
    const int warp_m = wid & 1;     // 64 rows each
    const int warp_n = wid >> 1;    // 32 cols each
    const int bm = blockIdx.y * 128;
    const int bn = blockIdx.x * 64;
    const int KG = K >> 3;
    const int T0 = bm >> 4;
    const int J0 = bn >> 3;

    float acc[4][4][4];
    #pragma unroll
    for (int i = 0; i < 4; i++)
        #pragma unroll
        for (int j = 0; j < 4; j++)
            #pragma unroll
            for (int r = 0; r < 4; r++) acc[i][j][r] = 0.f;

    const int nk = K >> 4;   // 16-deep steps (2 G-blocks each)

#define LOAD_TILE(kt, stg) do {                                                \
        const int G0 = (kt) * 2;                                               \
        float* sa = S + (stg) * STAGE_WORDS;                                   \
        _Pragma("unroll")                                                      \
        for (int c2 = 0; c2 < 4; c2++) {                                       \
            int o = c2 * 128 + tid;                                            \
            int t = o >> 6, off = o & 63;                                      \
            size_t so = ((size_t)((T0 + t) * KG + G0)) * 128 + (size_t)off * 4;\
            uint32_t d = smem_u32(sa + (t * 256 + off * 4));                   \
            CP_ASYNC16(d,            Ah + so);                                 \
            CP_ASYNC16(d + 2048 * 4, Al + so);                                 \
        }                                                                      \
        _Pragma("unroll")                                                      \
        for (int c2 = 0; c2 < 2; c2++) {                                       \
            int o = c2 * 128 + tid;                                            \
            int j = o >> 5, off = o & 31;                                      \
            size_t so = ((size_t)((J0 + j) * KG + G0)) * 64 + (size_t)off * 4; \
            uint32_t d = smem_u32(sa + (4096 + j * 128 + off * 4));            \
            CP_ASYNC16(d,            Bh + so);                                 \
            CP_ASYNC16(d + 1024 * 4, Bl + so);                                 \
        }                                                                      \
    } while (0)

    // prologue: stages 0,1 in flight
    LOAD_TILE(0, 0); CP_COMMIT();
    LOAD_TILE(1, 1); CP_COMMIT();

    for (int kt = 0; kt < nk; kt++) {
        CP_WAIT1();
        __syncthreads();

        const float* st = S + (kt % STAGES) * STAGE_WORDS;

        #pragma unroll
        for (int g = 0; g < 2; g++) {
            // B fragments: 4 LDS.64 hi + 4 LDS.64 lo
            uint2 bh[4], bl[4];
            #pragma unroll
            for (int j = 0; j < 4; j++) {
                const float* bp = st + 4096 + (warp_n * 4 + j) * 128 + g * 64 + lane * 2;
                bh[j] = *(const uint2*)bp;
                bl[j] = *(const uint2*)(bp + 1024);
            }
            #pragma unroll
            for (int i = 0; i < 4; i++) {
                const float* ap = st + (warp_m * 4 + i) * 256 + g * 128 + lane * 4;
                uint4 ah4 = *(const uint4*)ap;
                uint4 al4 = *(const uint4*)(ap + 2048);
                uint32_t ah[4] = {ah4.x, ah4.y, ah4.z, ah4.w};
                uint32_t al[4] = {al4.x, al4.y, al4.z, al4.w};
                #pragma unroll
                for (int j = 0; j < 4; j++) {
                    uint32_t bhj[2] = {bh[j].x, bh[j].y};
                    mma_tf32(acc[i][j], ah, bhj);
                }
                #pragma unroll
                for (int j = 0; j < 4; j++) {
                    uint32_t blj[2] = {bl[j].x, bl[j].y};
                    mma_tf32(acc[i][j], ah, blj);
                }
                #pragma unroll
                for (int j = 0; j < 4; j++) {
                    uint32_t bhj[2] = {bh[j].x, bh[j].y};
                    mma_tf32(acc[i][j], al, bhj);
                }
            }
        }
        __syncthreads();

        const int nt = kt + 2;
        if (nt < nk) LOAD_TILE(nt, nt % STAGES);
        CP_COMMIT();
    }
#undef LOAD_TILE

    // epilogue
    #pragma unroll
    for (int i = 0; i < 4; i++) {
        const int row0 = bm + warp_m * 64 + i * 16 + gq;
        #pragma unroll
        for (int j = 0; j < 4; j++) {
            const int col = bn + warp_n * 32 + j * 8 + tig * 2;
            float v0 = acc[i][j][0], v1 = acc[i][j][1];
            float v2 = acc[i][j][2], v3 = acc[i][j][3];
            if (SILU) { v0 = silu_f(v0); v1 = silu_f(v1); v2 = silu_f(v2); v3 = silu_f(v3); }
            if (SPLIT_OUT) {
                store_afrag(Ch, Cl, row0,     col,     N, v0);
                store_afrag(Ch, Cl, row0,     col + 1, N, v1);
                store_afrag(Ch, Cl, row0 + 8, col,     N, v2);
                store_afrag(Ch, Cl, row0 + 8, col + 1, N, v3);
            } else {
                *(float2*)&C[(size_t)row0 * N + col]       = make_float2(v0, v1);
                *(float2*)&C[(size_t)(row0 + 8) * N + col] = make_float2(v2, v3);
            }
        }
    }
}

// ---------------------------------------------------------------
// small-weight transpose: dst[c*rows + r] = src[r*cols + c]
// ---------------------------------------------------------------
__global__ void transpose_small(const float* __restrict__ src, float* __restrict__ dst,
                                int rows, int cols)
{
    int i = blockIdx.x * blockDim.x + threadIdx.x;
    if (i < rows * cols) {
        int r = i / cols, c = i % cols;
        dst[(size_t)c * rows + r] = src[i];
    }
}

// ---------------------------------------------------------------
// depthwise causal conv (K=4) + bias + SiLU.
// ---------------------------------------------------------------
__global__ void conv_silu_kernel(const float* __restrict__ conv_w,
                                 const float* __restrict__ conv_b)
{
    int idx = blockIdx.x * blockDim.x + threadIdx.x;  // over TOK*DI
    if (idx >= TOK * DI) return;
    int d = idx % DI;
    int t = idx / DI;
    int l = t % LL;
    int b = t / LL;

    float4 w = *(const float4*)&conv_w[d * KC];
    float acc = conv_b[d];
    const float* Pb = g_P + (size_t)b * LL * N2 + d;
    float wj[4] = {w.x, w.y, w.z, w.w};
    #pragma unroll
    for (int j = 0; j < KC; j++) {
        int ls = l - (KC - 1) + j;
        if (ls >= 0) acc = fmaf(wj[j], Pb[(size_t)ls * N2], acc);
    }
    g_hsc[idx] = silu_f(acc);
}

// ---------------------------------------------------------------
// x_proj: ssmp[t,k] = sum_d hsc[t,d] * xwT[d,k],  k in [0,80)
// ---------------------------------------------------------------
__global__ void xproj_kernel()
{
    __shared__ float sh[DI];
    const int t = blockIdx.x;
    for (int i = threadIdx.x; i < DI; i += blockDim.x)
        sh[i] = g_hsc[(size_t)t * DI + i];
    __syncthreads();
    const int k = threadIdx.x;
    if (k < 80) {
        float acc = 0.f;
        #pragma unroll 8
        for (int d = 0; d < DI; d++)
            acc = fmaf(sh[d], g_xwT[d * 80 + k], acc);
        g_ssmp[(size_t)t * 80 + k] = acc;
    }
}

// ---------------------------------------------------------------
// dt: dt[t,d] = softplus( ts[t,:] @ dt_w[d,:] + dt_b[d] )
// ---------------------------------------------------------------
__global__ void dt_kernel(const float* __restrict__ dt_b)
{
    __shared__ float ts[RR];
    const int t = blockIdx.x;
    if (threadIdx.x < RR) ts[threadIdx.x] = g_ssmp[(size_t)t * 80 + threadIdx.x];
    __syncthreads();
    for (int d = threadIdx.x; d < DI; d += blockDim.x) {
        float acc = dt_b[d];
        #pragma unroll
        for (int r = 0; r < RR; r++)
            acc = fmaf(ts[r], g_dtwT[r * DI + d], acc);
        float sp = (acc > 20.f) ? acc : log1pf(expf(acc));
        g_dt[(size_t)t * DI + d] = sp;
    }
}

// ---------------------------------------------------------------
// selective scan. thread per (b,d). writes z directly as frag hi/lo.
// ---------------------------------------------------------------
__global__ void scan_kernel(const float* __restrict__ A_log,
                            const float* __restrict__ Dp)
{
    const int d = blockIdx.x * blockDim.x + threadIdx.x;
    const int b = blockIdx.y;
    if (d >= DI) return;

    float Arow[NN];
    #pragma unroll
    for (int n = 0; n < NN; n++) Arow[n] = -expf(A_log[d * NN + n]);
    const float Dd = Dp[d];

    float s[NN];
    #pragma unroll
    for (int n = 0; n < NN; n++) s[n] = 0.f;

    for (int l = 0; l < LL; l++) {
        const size_t t = (size_t)b * LL + l;
        const float dtv = g_dt[t * DI + d];
        const float u   = g_hsc[t * DI + d];
        const float gte = g_P[t * N2 + DI + d];
        const float* bc = g_ssmp + t * 80 + RR;
        const float dtu = dtv * u;
        float y = 0.f;
        #pragma unroll
        for (int n = 0; n < NN; n++) {
            const float Bn = __ldg(bc + n);
            const float Cn = __ldg(bc + NN + n);
            const float dA = __expf(dtv * Arow[n]);
            s[n] = fmaf(dA, s[n], dtu * Bn);
            y = fmaf(s[n], Cn, y);
        }
        float zz = fmaf(u, Dd, y);
        zz *= silu_f(gte);
        store_afrag(g_zh, g_zl, (int)t, d, DI, zz);
    }
}

// ---------------------------------------------------------------
extern "C" void kernel_launch(void* const* d_in, const int* in_sizes, int n_in,
                              void* d_out, int out_size)
{
    const float* x          = (const float*)d_in[0];
    const float* in_up_w    = (const float*)d_in[1];
    const float* in_down_w  = (const float*)d_in[2];
    const float* conv_w     = (const float*)d_in[3];
    const float* conv_b     = (const float*)d_in[4];
    const float* x_proj_w   = (const float*)d_in[5];
    const float* dt_w       = (const float*)d_in[6];
    const float* dt_b       = (const float*)d_in[7];
    const float* A_log      = (const float*)d_in[8];
    const float* Dp         = (const float*)d_in[9];
    const float* out_up_w   = (const float*)d_in[10];
    const float* out_down_w = (const float*)d_in[11];
    float* out = (float*)d_out;

    float *xh, *xl, *w1h, *w1l, *t1h, *t1l, *w2h, *w2l;
    float *zh, *zl, *w3h, *w3l, *t2h, *t2l, *w4h, *w4l;
    float *P, *xwT, *dtwT;
    cudaGetSymbolAddress((void**)&xh,  g_xh);  cudaGetSymbolAddress((void**)&xl,  g_xl);
    cudaGetSymbolAddress((void**)&w1h, g_w1h); cudaGetSymbolAddress((void**)&w1l, g_w1l);
    cudaGetSymbolAddress((void**)&t1h, g_t1h); cudaGetSymbolAddress((void**)&t1l, g_t1l);
    cudaGetSymbolAddress((void**)&w2h, g_w2h); cudaGetSymbolAddress((void**)&w2l, g_w2l);
    cudaGetSymbolAddress((void**)&zh,  g_zh);  cudaGetSymbolAddress((void**)&zl,  g_zl);
    cudaGetSymbolAddress((void**)&w3h, g_w3h); cudaGetSymbolAddress((void**)&w3l, g_w3l);
    cudaGetSymbolAddress((void**)&t2h, g_t2h); cudaGetSymbolAddress((void**)&t2l, g_t2l);
    cudaGetSymbolAddress((void**)&w4h, g_w4h); cudaGetSymbolAddress((void**)&w4l, g_w4l);
    cudaGetSymbolAddress((void**)&P,   g_P);
    cudaGetSymbolAddress((void**)&xwT,  g_xwT);
    cudaGetSymbolAddress((void**)&dtwT, g_dtwT);

    static int attr_done = 0;
    if (!attr_done) {
        cudaFuncSetAttribute(gemm_frag<true,  true >, cudaFuncAttributeMaxDynamicSharedMemorySize, GSMEM_BYTES);
        cudaFuncSetAttribute(gemm_frag<false, false>, cudaFuncAttributeMaxDynamicSharedMemorySize, GSMEM_BYTES);
        attr_done = 1;
    }

    // operand splits (frag-major hi/lo)
    splitA_frag<<<(TOK*HH + 255)/256, 256>>>(x, xh, xl, TOK, HH);
    splitB_frag<<<((size_t)N1*HH + 255)/256, 256>>>(in_up_w,    w1h, w1l, N1, HH);
    splitB_frag<<<((size_t)N2*N1 + 255)/256, 256>>>(in_down_w,  w2h, w2l, N2, N1);
    splitB_frag<<<((size_t)N3*DI + 255)/256, 256>>>(out_up_w,   w3h, w3l, N3, DI);
    splitB_frag<<<((size_t)HH*N3 + 255)/256, 256>>>(out_down_w, w4h, w4l, HH, N3);
    transpose_small<<<(80*DI + 255)/256, 256>>>(x_proj_w, xwT, 80, DI);
    transpose_small<<<(DI*RR + 255)/256, 256>>>(dt_w, dtwT, DI, RR);

    // 1) up-proj + SiLU -> t1 frags
    gemm_frag<true,  true ><<<dim3(N1/64, TOK/128), 128, GSMEM_BYTES>>>(
        xh, xl, w1h, w1l, nullptr, t1h, t1l, TOK, N1, HH);
    // 2) down-proj -> P (row-major)
    gemm_frag<false, false><<<dim3(N2/64, TOK/128), 128, GSMEM_BYTES>>>(
        t1h, t1l, w2h, w2l, P, nullptr, nullptr, TOK, N2, N1);
    // 3) conv + SiLU
    conv_silu_kernel<<<(TOK*DI + 255)/256, 256>>>(conv_w, conv_b);
    // 4) x_proj
    xproj_kernel<<<TOK, 96>>>();
    // 5) dt
    dt_kernel<<<TOK, 256>>>(dt_b);
    // 6) scan -> z frags
    scan_kernel<<<dim3(DI/128, BB), 128>>>(A_log, Dp);
    // 7) out up-proj + SiLU -> t2 frags
    gemm_frag<true,  true ><<<dim3(N3/64, TOK/128), 128, GSMEM_BYTES>>>(
        zh, zl, w3h, w3l, nullptr, t2h, t2l, TOK, N3, DI);
    // 8) out down-proj -> out (row-major)
    gemm_frag<false, false><<<dim3(HH/64, TOK/128), 128, GSMEM_BYTES>>>(
        t2h, t2l, w4h, w4l, out, nullptr, nullptr, TOK, HH, N3);
}